// round 1
// baseline (speedup 1.0000x reference)
#include <cuda_runtime.h>
#include <cuda_bf16.h>
#include <cstdint>

// Problem constants (fixed by the reference)
#define NUM_TOKENS 131072
#define NUM_EXPERTS 256
#define TOPK 8

// Monotone map: float -> uint32 such that float order == unsigned order
__device__ __forceinline__ unsigned int f2ord(float f) {
    unsigned int u = __float_as_uint(f);
    return (u & 0x80000000u) ? ~u : (u | 0x80000000u);
}
__device__ __forceinline__ float ord2f(unsigned int o) {
    unsigned int u = (o & 0x80000000u) ? (o ^ 0x80000000u) : ~o;
    return __uint_as_float(u);
}

__global__ void __launch_bounds__(256, 8)
moe_topk_softmax_kernel(const float* __restrict__ gating,
                        float* __restrict__ out) {
    const int warp = (blockIdx.x * (blockDim.x >> 5)) + (threadIdx.x >> 5);
    const int lane = threadIdx.x & 31;
    if (warp >= NUM_TOKENS) return;

    // Coalesced row load: 64 float4 per row; lane reads float4 #lane and #(lane+32)
    const float4* row = reinterpret_cast<const float4*>(gating + (size_t)warp * NUM_EXPERTS);
    float4 a = __ldg(&row[lane]);
    float4 b = __ldg(&row[lane + 32]);

    float v[8] = {a.x, a.y, a.z, a.w, b.x, b.y, b.z, b.w};

    // Pack into 64-bit keys: high 32 = ordered float, low bits = (255 - index)
    // so a single unsigned max picks max value with LOWEST index tie-break.
    unsigned long long key[8];
#pragma unroll
    for (int j = 0; j < 8; j++) {
        int gidx = (j < 4) ? (lane * 4 + j) : (128 + lane * 4 + (j - 4));
        key[j] = ((unsigned long long)f2ord(v[j]) << 32) | (unsigned)(255 - gidx);
    }

    float topv[TOPK];
    int   topi[TOPK];

#pragma unroll
    for (int r = 0; r < TOPK; r++) {
        // local max over this lane's 8 keys
        unsigned long long m = key[0];
#pragma unroll
        for (int j = 1; j < 8; j++) m = (key[j] > m) ? key[j] : m;
        // warp max-reduce
#pragma unroll
        for (int o = 16; o > 0; o >>= 1) {
            unsigned long long other = __shfl_xor_sync(0xffffffffu, m, o);
            m = (other > m) ? other : m;
        }
        int gidx = 255 - (int)(m & 0xFFu);
        topv[r] = ord2f((unsigned int)(m >> 32));
        topi[r] = gidx;
        // clear the winner (only its owner lane holds it; index is unique)
#pragma unroll
        for (int j = 0; j < 8; j++) {
            int g = (j < 4) ? (lane * 4 + j) : (128 + lane * 4 + (j - 4));
            if (g == gidx) key[j] = 0ull;
        }
    }

    // Softmax denominator: sum over all 256 of exp(x - rowmax)
    const float rowmax = topv[0];
    float s = 0.f;
#pragma unroll
    for (int j = 0; j < 8; j++) s += __expf(v[j] - rowmax);
#pragma unroll
    for (int o = 16; o > 0; o >>= 1) s += __shfl_xor_sync(0xffffffffu, s, o);
    const float inv = 1.0f / s;

    // Output: [weights (TOKENS*8) | indices-as-float (TOKENS*8)]
    // lanes 0..7 write weights, lanes 8..15 write indices (unrolled selects,
    // no dynamic register indexing).
    float outval = 0.f;
#pragma unroll
    for (int r = 0; r < TOPK; r++) {
        float w = __expf(topv[r] - rowmax) * inv;
        outval = (lane == r)        ? w                 : outval;
        outval = (lane == r + TOPK) ? (float)topi[r]    : outval;
    }
    if (lane < TOPK) {
        out[(size_t)warp * TOPK + lane] = outval;
    } else if (lane < 2 * TOPK) {
        out[(size_t)NUM_TOKENS * TOPK + (size_t)warp * TOPK + (lane - TOPK)] = outval;
    }
}

extern "C" void kernel_launch(void* const* d_in, const int* in_sizes, int n_in,
                              void* d_out, int out_size) {
    const float* gating = (const float*)d_in[0];
    float* out = (float*)d_out;
    // 8 warps (8 tokens) per 256-thread block
    const int blocks = NUM_TOKENS / 8;
    moe_topk_softmax_kernel<<<blocks, 256>>>(gating, out);
}

// round 3
// speedup vs baseline: 1.9750x; 1.9750x over previous
#include <cuda_runtime.h>
#include <cuda_bf16.h>
#include <cstdint>

#define NUM_TOKENS 131072
#define NUM_EXPERTS 256
#define TOPK 8

// Monotone map: float -> uint32 such that float order == unsigned order
__device__ __forceinline__ unsigned int f2ord(float f) {
    unsigned int u = __float_as_uint(f);
    return u ^ ((unsigned int)((int)u >> 31) | 0x80000000u);
}
__device__ __forceinline__ float ord2f(unsigned int o) {
    unsigned int u = o ^ (~(unsigned int)((int)o >> 31) | 0x80000000u);
    return __uint_as_float(u);
}

__global__ void __launch_bounds__(256, 4)
moe_topk_softmax_kernel(const float* __restrict__ gating,
                        float* __restrict__ out) {
    const int warp = (blockIdx.x * (blockDim.x >> 5)) + (threadIdx.x >> 5);
    const int lane = threadIdx.x & 31;

    // Coalesced row load: 64 float4 per row; lane reads float4 #lane and #(lane+32)
    const float4* row = reinterpret_cast<const float4*>(gating + (size_t)warp * NUM_EXPERTS);
    float4 a = __ldg(&row[lane]);
    float4 b = __ldg(&row[lane + 32]);

    float v[8] = {a.x, a.y, a.z, a.w, b.x, b.y, b.z, b.w};

    // Packed 64-bit keys: hi = ordered float, lo = (255 - expert_idx)
    // => unsigned max picks max value with LOWEST index tie-break.
    unsigned long long key[8];
#pragma unroll
    for (int j = 0; j < 8; j++) {
        int gidx = (j < 4) ? (lane * 4 + j) : (128 + lane * 4 + (j - 4));
        key[j] = ((unsigned long long)f2ord(v[j]) << 32) | (unsigned)(255 - gidx);
    }

    // Sort lane-local 8 keys DESCENDING with a 19-CEX sorting network (Bose-Nelson).
#define CEX(i, j) { unsigned long long lo_ = min(key[i], key[j]); \
                    key[i] = max(key[i], key[j]); key[j] = lo_; }
    CEX(0,1) CEX(2,3) CEX(4,5) CEX(6,7)
    CEX(0,2) CEX(1,3) CEX(4,6) CEX(5,7)
    CEX(1,2) CEX(5,6) CEX(0,4) CEX(3,7)
    CEX(1,5) CEX(2,6)
    CEX(1,4) CEX(3,6)
    CEX(2,4) CEX(3,5)
    CEX(3,4)
#undef CEX

    // 8 rounds of single-instruction warp reductions on the head element.
    unsigned int topo[TOPK];  // ordered value of winner (warp-uniform)
    unsigned int topl[TOPK];  // 255 - winner index    (warp-uniform)
#pragma unroll
    for (int r = 0; r < TOPK; r++) {
        unsigned int hi0 = (unsigned int)(key[0] >> 32);
        unsigned int lo0 = (unsigned int)key[0];
        unsigned int m  = __reduce_max_sync(0xffffffffu, hi0);
        bool win        = (hi0 == m);
        unsigned int wl = __reduce_max_sync(0xffffffffu, win ? lo0 : 0u);
        topo[r] = m;
        topl[r] = wl;
        bool adv = win && (lo0 == wl);
        // winner lane advances: shift its sorted list up by one
#pragma unroll
        for (int j = 0; j < 7; j++) key[j] = adv ? key[j + 1] : key[j];
        key[7] = adv ? 0ull : key[7];
    }

    // Softmax denominator over all 256 (row max = first winner)
    const float rowmax = ord2f(topo[0]);
    float s = 0.f;
#pragma unroll
    for (int j = 0; j < 8; j++) s += __expf(v[j] - rowmax);
#pragma unroll
    for (int o = 16; o > 0; o >>= 1) s += __shfl_xor_sync(0xffffffffu, s, o);
    const float inv = 1.0f / s;

    // Warp-uniform results -> vectorized output.
    // Layout: [weights (TOKENS*8) | indices-as-float (TOKENS*8)]
    float w[TOPK], fi[TOPK];
#pragma unroll
    for (int r = 0; r < TOPK; r++) {
        w[r]  = __expf(ord2f(topo[r]) - rowmax) * inv;
        fi[r] = (float)(int)(255u - topl[r]);
    }
    float* wbase = out + (size_t)warp * TOPK;
    float* ibase = out + (size_t)NUM_TOKENS * TOPK + (size_t)warp * TOPK;
    if (lane == 0) *reinterpret_cast<float4*>(wbase)     = make_float4(w[0], w[1], w[2], w[3]);
    if (lane == 1) *reinterpret_cast<float4*>(wbase + 4) = make_float4(w[4], w[5], w[6], w[7]);
    if (lane == 2) *reinterpret_cast<float4*>(ibase)     = make_float4(fi[0], fi[1], fi[2], fi[3]);
    if (lane == 3) *reinterpret_cast<float4*>(ibase + 4) = make_float4(fi[4], fi[5], fi[6], fi[7]);
}

extern "C" void kernel_launch(void* const* d_in, const int* in_sizes, int n_in,
                              void* d_out, int out_size) {
    const float* gating = (const float*)d_in[0];
    float* out = (float*)d_out;
    // 8 warps (8 tokens) per 256-thread block
    const int blocks = NUM_TOKENS / 8;
    moe_topk_softmax_kernel<<<blocks, 256>>>(gating, out);
}

// round 4
// speedup vs baseline: 1.9778x; 1.0014x over previous
#include <cuda_runtime.h>
#include <cuda_bf16.h>
#include <cstdint>

#define NUM_TOKENS 131072
#define NUM_EXPERTS 256
#define TOPK 8

// Monotone map: float -> uint32 such that float order == unsigned order
__device__ __forceinline__ unsigned int f2ord(float f) {
    unsigned int u = __float_as_uint(f);
    return u ^ ((unsigned int)((int)u >> 31) | 0x80000000u);
}
__device__ __forceinline__ float ord2f(unsigned int o) {
    unsigned int u = o ^ (~(unsigned int)((int)o >> 31) | 0x80000000u);
    return __uint_as_float(u);
}

__global__ void __launch_bounds__(256, 4)
moe_topk_softmax_kernel(const float* __restrict__ gating,
                        float* __restrict__ out) {
    const int warp = (blockIdx.x * (blockDim.x >> 5)) + (threadIdx.x >> 5);
    const int lane = threadIdx.x & 31;

    // Coalesced row load: 64 float4 per row; lane reads float4 #lane and #(lane+32)
    const float4* row = reinterpret_cast<const float4*>(gating + (size_t)warp * NUM_EXPERTS);
    float4 a = __ldg(&row[lane]);
    float4 b = __ldg(&row[lane + 32]);

    float v[8] = {a.x, a.y, a.z, a.w, b.x, b.y, b.z, b.w};

    // Packed 64-bit keys: hi = ordered float, lo = (255 - expert_idx)
    // => unsigned max picks max value with LOWEST index tie-break.
    unsigned long long key[8];
#pragma unroll
    for (int j = 0; j < 8; j++) {
        int gidx = (j < 4) ? (lane * 4 + j) : (128 + lane * 4 + (j - 4));
        key[j] = ((unsigned long long)f2ord(v[j]) << 32) | (unsigned)(255 - gidx);
    }

    // Sort lane-local 8 keys DESCENDING with a 19-CEX sorting network (Bose-Nelson).
#define CEX(i, j) { unsigned long long lo_ = min(key[i], key[j]); \
                    key[i] = max(key[i], key[j]); key[j] = lo_; }
    CEX(0,1) CEX(2,3) CEX(4,5) CEX(6,7)
    CEX(0,2) CEX(1,3) CEX(4,6) CEX(5,7)
    CEX(1,2) CEX(5,6) CEX(0,4) CEX(3,7)
    CEX(1,5) CEX(2,6)
    CEX(1,4) CEX(3,6)
    CEX(2,4) CEX(3,5)
    CEX(3,4)
#undef CEX

    // 8 rounds of single-instruction warp reductions on the head element.
    unsigned int topo[TOPK];  // ordered value of winner (warp-uniform)
    unsigned int topl[TOPK];  // 255 - winner index    (warp-uniform)
#pragma unroll
    for (int r = 0; r < TOPK; r++) {
        unsigned int hi0 = (unsigned int)(key[0] >> 32);
        unsigned int lo0 = (unsigned int)key[0];
        unsigned int m  = __reduce_max_sync(0xffffffffu, hi0);
        bool win        = (hi0 == m);
        unsigned int wl = __reduce_max_sync(0xffffffffu, win ? lo0 : 0u);
        topo[r] = m;
        topl[r] = wl;
        bool adv = win && (lo0 == wl);
        // winner lane advances: shift its sorted list up by one
#pragma unroll
        for (int j = 0; j < 7; j++) key[j] = adv ? key[j + 1] : key[j];
        key[7] = adv ? 0ull : key[7];
    }

    // Softmax denominator over all 256 (row max = first winner)
    const float rowmax = ord2f(topo[0]);
    float s = 0.f;
#pragma unroll
    for (int j = 0; j < 8; j++) s += __expf(v[j] - rowmax);
#pragma unroll
    for (int o = 16; o > 0; o >>= 1) s += __shfl_xor_sync(0xffffffffu, s, o);
    const float inv = 1.0f / s;

    // Warp-uniform results -> vectorized output.
    // Layout: [weights (TOKENS*8) | indices-as-float (TOKENS*8)]
    float w[TOPK], fi[TOPK];
#pragma unroll
    for (int r = 0; r < TOPK; r++) {
        w[r]  = __expf(ord2f(topo[r]) - rowmax) * inv;
        fi[r] = (float)(int)(255u - topl[r]);
    }
    float* wbase = out + (size_t)warp * TOPK;
    float* ibase = out + (size_t)NUM_TOKENS * TOPK + (size_t)warp * TOPK;
    if (lane == 0) *reinterpret_cast<float4*>(wbase)     = make_float4(w[0], w[1], w[2], w[3]);
    if (lane == 1) *reinterpret_cast<float4*>(wbase + 4) = make_float4(w[4], w[5], w[6], w[7]);
    if (lane == 2) *reinterpret_cast<float4*>(ibase)     = make_float4(fi[0], fi[1], fi[2], fi[3]);
    if (lane == 3) *reinterpret_cast<float4*>(ibase + 4) = make_float4(fi[4], fi[5], fi[6], fi[7]);
}

extern "C" void kernel_launch(void* const* d_in, const int* in_sizes, int n_in,
                              void* d_out, int out_size) {
    const float* gating = (const float*)d_in[0];
    float* out = (float*)d_out;
    // 8 warps (8 tokens) per 256-thread block
    const int blocks = NUM_TOKENS / 8;
    moe_topk_softmax_kernel<<<blocks, 256>>>(gating, out);
}

// round 5
// speedup vs baseline: 1.9812x; 1.0017x over previous
#include <cuda_runtime.h>
#include <cuda_bf16.h>
#include <cstdint>

#define NUM_TOKENS 131072
#define NUM_EXPERTS 256
#define TOPK 8

// Monotone map: float -> uint32 such that float order == unsigned order
__device__ __forceinline__ unsigned int f2ord(float f) {
    unsigned int u = __float_as_uint(f);
    return u ^ ((unsigned int)((int)u >> 31) | 0x80000000u);
}
__device__ __forceinline__ float ord2f(unsigned int o) {
    unsigned int u = o ^ (~(unsigned int)((int)o >> 31) | 0x80000000u);
    return __uint_as_float(u);
}

__global__ void __launch_bounds__(256, 4)
moe_topk_softmax_kernel(const float* __restrict__ gating,
                        float* __restrict__ out) {
    const int warp = (blockIdx.x * (blockDim.x >> 5)) + (threadIdx.x >> 5);
    const int lane = threadIdx.x & 31;

    // Coalesced row load: 64 float4 per row; lane reads float4 #lane and #(lane+32)
    const float4* row = reinterpret_cast<const float4*>(gating + (size_t)warp * NUM_EXPERTS);
    float4 a = __ldg(&row[lane]);
    float4 b = __ldg(&row[lane + 32]);

    float v[8] = {a.x, a.y, a.z, a.w, b.x, b.y, b.z, b.w};

    // Packed 64-bit keys: hi = ordered float, lo = (255 - expert_idx)
    // => unsigned max picks max value with LOWEST index tie-break.
    unsigned long long key[8];
#pragma unroll
    for (int j = 0; j < 8; j++) {
        int gidx = (j < 4) ? (lane * 4 + j) : (128 + lane * 4 + (j - 4));
        key[j] = ((unsigned long long)f2ord(v[j]) << 32) | (unsigned)(255 - gidx);
    }

    // Sort lane-local 8 keys DESCENDING with a 19-CEX sorting network (Bose-Nelson).
#define CEX(i, j) { unsigned long long lo_ = min(key[i], key[j]); \
                    key[i] = max(key[i], key[j]); key[j] = lo_; }
    CEX(0,1) CEX(2,3) CEX(4,5) CEX(6,7)
    CEX(0,2) CEX(1,3) CEX(4,6) CEX(5,7)
    CEX(1,2) CEX(5,6) CEX(0,4) CEX(3,7)
    CEX(1,5) CEX(2,6)
    CEX(1,4) CEX(3,6)
    CEX(2,4) CEX(3,5)
    CEX(3,4)
#undef CEX

    // 8 rounds of single-instruction warp reductions on the head element.
    unsigned int topo[TOPK];  // ordered value of winner (warp-uniform)
    unsigned int topl[TOPK];  // 255 - winner index    (warp-uniform)
#pragma unroll
    for (int r = 0; r < TOPK; r++) {
        unsigned int hi0 = (unsigned int)(key[0] >> 32);
        unsigned int lo0 = (unsigned int)key[0];
        unsigned int m  = __reduce_max_sync(0xffffffffu, hi0);
        bool win        = (hi0 == m);
        unsigned int wl = __reduce_max_sync(0xffffffffu, win ? lo0 : 0u);
        topo[r] = m;
        topl[r] = wl;
        bool adv = win && (lo0 == wl);
        // winner lane advances: shift its sorted list up by one
#pragma unroll
        for (int j = 0; j < 7; j++) key[j] = adv ? key[j + 1] : key[j];
        key[7] = adv ? 0ull : key[7];
    }

    // Softmax denominator over all 256 (row max = first winner)
    const float rowmax = ord2f(topo[0]);
    float s = 0.f;
#pragma unroll
    for (int j = 0; j < 8; j++) s += __expf(v[j] - rowmax);
#pragma unroll
    for (int o = 16; o > 0; o >>= 1) s += __shfl_xor_sync(0xffffffffu, s, o);
    const float inv = 1.0f / s;

    // Warp-uniform results -> vectorized output.
    // Layout: [weights (TOKENS*8) | indices-as-float (TOKENS*8)]
    float w[TOPK], fi[TOPK];
#pragma unroll
    for (int r = 0; r < TOPK; r++) {
        w[r]  = __expf(ord2f(topo[r]) - rowmax) * inv;
        fi[r] = (float)(int)(255u - topl[r]);
    }
    float* wbase = out + (size_t)warp * TOPK;
    float* ibase = out + (size_t)NUM_TOKENS * TOPK + (size_t)warp * TOPK;
    if (lane == 0) *reinterpret_cast<float4*>(wbase)     = make_float4(w[0], w[1], w[2], w[3]);
    if (lane == 1) *reinterpret_cast<float4*>(wbase + 4) = make_float4(w[4], w[5], w[6], w[7]);
    if (lane == 2) *reinterpret_cast<float4*>(ibase)     = make_float4(fi[0], fi[1], fi[2], fi[3]);
    if (lane == 3) *reinterpret_cast<float4*>(ibase + 4) = make_float4(fi[4], fi[5], fi[6], fi[7]);
}

extern "C" void kernel_launch(void* const* d_in, const int* in_sizes, int n_in,
                              void* d_out, int out_size) {
    const float* gating = (const float*)d_in[0];
    float* out = (float*)d_out;
    // 8 warps (8 tokens) per 256-thread block
    const int blocks = NUM_TOKENS / 8;
    moe_topk_softmax_kernel<<<blocks, 256>>>(gating, out);
}

// round 7
// speedup vs baseline: 2.4054x; 1.2141x over previous
#include <cuda_runtime.h>
#include <cuda_bf16.h>
#include <cstdint>

#define NUM_TOKENS 131072
#define NUM_EXPERTS 256
#define TOPK 8

// Monotone map on raw float bits: float order == unsigned order
__device__ __forceinline__ unsigned int ord_bits(unsigned int u) {
    return u ^ ((unsigned int)((int)u >> 31) | 0x80000000u);
}
__device__ __forceinline__ float ord2f(unsigned int o) {
    unsigned int u = o ^ (~(unsigned int)((int)o >> 31) | 0x80000000u);
    return __uint_as_float(u);
}

__global__ void __launch_bounds__(256, 4)
moe_topk_softmax_kernel(const float* __restrict__ gating,
                        float* __restrict__ out) {
    __shared__ unsigned long long buf[8][64];   // per-warp survivor buffer
    const int wib  = threadIdx.x >> 5;
    const int warp = blockIdx.x * 8 + wib;
    const int lane = threadIdx.x & 31;

    // Coalesced row load: 64 float4 per row; lane reads float4 #lane and #(lane+32)
    const float4* row = reinterpret_cast<const float4*>(gating + (size_t)warp * NUM_EXPERTS);
    float4 A = __ldg(&row[lane]);
    float4 B = __ldg(&row[lane + 32]);
    float v[8] = {A.x, A.y, A.z, A.w, B.x, B.y, B.z, B.w};

    // ---- Phase 1: per-lane max, then m8 = 8th largest of the 32 lane maxima ----
    float lm = v[0];
#pragma unroll
    for (int j = 1; j < 8; j++) lm = fmaxf(lm, v[j]);

    // Warp bitonic sort (ascending by lane id) of the 32 lane maxima (no NaNs: gaussian input)
    float s = lm;
#pragma unroll
    for (int k = 2; k <= 32; k <<= 1) {
#pragma unroll
        for (int j = k >> 1; j > 0; j >>= 1) {
            float o = __shfl_xor_sync(0xffffffffu, s, j);
            bool up    = ((lane & k) == 0);
            bool lower = ((lane & j) == 0);
            s = (lower == up) ? fminf(s, o) : fmaxf(s, o);
        }
    }
    // ascending: lane 31 holds max; 8th largest lane-max at lane 24.
    // m8 <= t8 (lane maxima are a subset of all elements) => pruning < m8 keeps the true top-8.
    const float m8f = __shfl_sync(0xffffffffu, s, 24);

    // ---- Phase 2: flag survivors (v >= m8f), prefix-scan, compact into smem ----
    bool f[8];
    int c = 0;
#pragma unroll
    for (int j = 0; j < 8; j++) { f[j] = (v[j] >= m8f); c += f[j] ? 1 : 0; }

    int off = c;
#pragma unroll
    for (int d = 1; d < 32; d <<= 1) {
        int t = __shfl_up_sync(0xffffffffu, off, d);
        if (lane >= d) off += t;
    }
    const int S = __shfl_sync(0xffffffffu, off, 31);   // total survivors (typically ~10)
    off -= c;                                          // exclusive offset

    unsigned long long* wb = buf[wib];
#pragma unroll
    for (int j = 0; j < 8; j++) {
        if (f[j]) {
            int g = (j < 4) ? (lane * 4 + j) : (128 + lane * 4 + (j - 4));
            if (off < 64)
                wb[off] = ((unsigned long long)__float_as_uint(v[j]) << 32)
                        | (unsigned)(255 - g);
            off++;
        }
    }
    __syncwarp();   // survivor buffer visible warp-wide before reload

    // ---- Phase 3: top-8 of <=64 survivors, <=2 per lane ----
    // Key: hi = ordered value bits, lo = (255 - gidx)  => u64 max picks max value,
    // lowest index on ties (matches jax.lax.top_k stable ordering). Invalid = 0
    // (all real ordered values are > 0 for finite floats in gaussian range).
    unsigned long long a = 0ull, b = 0ull;
    if (lane < S) {
        unsigned long long k = wb[lane];
        a = ((unsigned long long)ord_bits((unsigned)(k >> 32)) << 32) | (unsigned)k;
    }
    if (lane + 32 < S) {
        unsigned long long k = wb[lane + 32];
        b = ((unsigned long long)ord_bits((unsigned)(k >> 32)) << 32) | (unsigned)k;
    }
    {
        unsigned long long mx = (a > b) ? a : b;
        b = (a > b) ? b : a;
        a = mx;
    }

    unsigned int topo[TOPK], topl[TOPK];
#pragma unroll
    for (int r = 0; r < TOPK; r++) {
        unsigned int hi = (unsigned)(a >> 32);
        unsigned int m  = __reduce_max_sync(0xffffffffu, hi);
        bool win        = (hi == m);
        unsigned int wl = __reduce_max_sync(0xffffffffu, win ? (unsigned)a : 0u);
        topo[r] = m;
        topl[r] = wl;
        bool adv = win && ((unsigned)a == wl);
        a = adv ? b : a;
        b = adv ? 0ull : b;
    }

    // ---- Softmax denominator over all 256 (row max = first winner) ----
    const float rowmax = ord2f(topo[0]);
    float sm = 0.f;
#pragma unroll
    for (int j = 0; j < 8; j++) sm += __expf(v[j] - rowmax);
#pragma unroll
    for (int o2 = 16; o2 > 0; o2 >>= 1) sm += __shfl_xor_sync(0xffffffffu, sm, o2);
    const float inv = 1.0f / sm;

    // ---- Warp-uniform results -> vectorized output ----
    // Layout: [weights (TOKENS*8) | indices-as-float (TOKENS*8)]
    float w[TOPK], fi[TOPK];
#pragma unroll
    for (int r = 0; r < TOPK; r++) {
        w[r]  = __expf(ord2f(topo[r]) - rowmax) * inv;
        fi[r] = (float)(int)(255u - topl[r]);
    }
    float* wbase = out + (size_t)warp * TOPK;
    float* ibase = out + (size_t)NUM_TOKENS * TOPK + (size_t)warp * TOPK;
    if (lane == 0) *reinterpret_cast<float4*>(wbase)     = make_float4(w[0], w[1], w[2], w[3]);
    if (lane == 1) *reinterpret_cast<float4*>(wbase + 4) = make_float4(w[4], w[5], w[6], w[7]);
    if (lane == 2) *reinterpret_cast<float4*>(ibase)     = make_float4(fi[0], fi[1], fi[2], fi[3]);
    if (lane == 3) *reinterpret_cast<float4*>(ibase + 4) = make_float4(fi[4], fi[5], fi[6], fi[7]);
}

extern "C" void kernel_launch(void* const* d_in, const int* in_sizes, int n_in,
                              void* d_out, int out_size) {
    const float* gating = (const float*)d_in[0];
    float* out = (float*)d_out;
    const int blocks = NUM_TOKENS / 8;   // 8 warps (tokens) per 256-thread block
    moe_topk_softmax_kernel<<<blocks, 256>>>(gating, out);
}

// round 8
// speedup vs baseline: 3.0690x; 1.2759x over previous
#include <cuda_runtime.h>
#include <cuda_bf16.h>
#include <cstdint>

#define NUM_TOKENS 131072
#define NUM_EXPERTS 256
#define TOPK 8
#define LOG2E 1.4426950408889634f

// Monotone map on raw float bits: float order == unsigned order
__device__ __forceinline__ unsigned int ord_bits(unsigned int u) {
    return u ^ ((unsigned int)((int)u >> 31) | 0x80000000u);
}
__device__ __forceinline__ float ord2f(unsigned int o) {
    unsigned int u = o ^ (~(unsigned int)((int)o >> 31) | 0x80000000u);
    return __uint_as_float(u);
}
__device__ __forceinline__ float ex2(float x) {
    float y; asm("ex2.approx.ftz.f32 %0, %1;" : "=f"(y) : "f"(x)); return y;
}

__global__ void __launch_bounds__(256, 4)
moe_topk_softmax_kernel(const float* __restrict__ gating,
                        float* __restrict__ out) {
    __shared__ unsigned long long buf[8][64];   // per-warp survivor buffer
    const int wib  = threadIdx.x >> 5;
    const int warp = blockIdx.x * 8 + wib;
    const int lane = threadIdx.x & 31;

    // Coalesced row load: 64 float4 per row; lane reads float4 #lane and #(lane+32)
    const float4* row = reinterpret_cast<const float4*>(gating + (size_t)warp * NUM_EXPERTS);
    float4 A = __ldg(&row[lane]);
    float4 B = __ldg(&row[lane + 32]);
    float v[8] = {A.x, A.y, A.z, A.w, B.x, B.y, B.z, B.w};

    // ---- Per-lane max ----
    float lm = v[0];
#pragma unroll
    for (int j = 1; j < 8; j++) lm = fmaxf(lm, v[j]);

    // ---- Cheap prune threshold: min over the 8 lane-quads of the quad max.
    // Each quad of 4 lanes covers 32 disjoint elements; the 8 quad-maxima are
    // 8 distinct elements, so their min <= true 8th-largest t8. Pruning < thr
    // therefore provably keeps the entire top-8.
    float qm = fmaxf(lm, __shfl_xor_sync(0xffffffffu, lm, 1));
    qm = fmaxf(qm, __shfl_xor_sync(0xffffffffu, qm, 2));
    float thr = fminf(qm, __shfl_xor_sync(0xffffffffu, qm, 4));
    thr = fminf(thr, __shfl_xor_sync(0xffffffffu, thr, 8));
    thr = fminf(thr, __shfl_xor_sync(0xffffffffu, thr, 16));

    // ---- Flags + exclusive prefix scan of survivor counts ----
    bool f[8];
    int c, off, S;
#define SCAN_FLAGS(T)                                                      \
    {                                                                      \
        c = 0;                                                             \
        _Pragma("unroll")                                                  \
        for (int j = 0; j < 8; j++) { f[j] = (v[j] >= (T)); c += f[j]; }   \
        off = c;                                                           \
        _Pragma("unroll")                                                  \
        for (int d = 1; d < 32; d <<= 1) {                                 \
            int t_ = __shfl_up_sync(0xffffffffu, off, d);                  \
            if (lane >= d) off += t_;                                      \
        }                                                                  \
        S = __shfl_sync(0xffffffffu, off, 31);                             \
        off -= c;                                                          \
    }
    SCAN_FLAGS(thr);

    // Rare fallback (~0.15% of tokens): exact 8th-largest of the 32 lane maxima
    // via warp bitonic sort guarantees survivors ~<=32.
    if (S > 64) {
        float s = lm;
#pragma unroll
        for (int k = 2; k <= 32; k <<= 1) {
#pragma unroll
            for (int j = k >> 1; j > 0; j >>= 1) {
                float o = __shfl_xor_sync(0xffffffffu, s, j);
                bool up    = ((lane & k) == 0);
                bool lower = ((lane & j) == 0);
                s = (lower == up) ? fminf(s, o) : fmaxf(s, o);
            }
        }
        float m8f = __shfl_sync(0xffffffffu, s, 24);  // 8th largest (ascending sort)
        SCAN_FLAGS(m8f);
    }
#undef SCAN_FLAGS

    // ---- Compact survivors into shared memory ----
    unsigned long long* wb = buf[wib];
#pragma unroll
    for (int j = 0; j < 8; j++) {
        if (f[j]) {
            int g = (j < 4) ? (lane * 4 + j) : (128 + lane * 4 + (j - 4));
            if (off < 64)
                wb[off] = ((unsigned long long)__float_as_uint(v[j]) << 32)
                        | (unsigned)(255 - g);
            off++;
        }
    }
    __syncwarp();

    // ---- Top-8 of <=64 survivors, <=2 per lane ----
    // Key: hi = ordered value bits, lo = (255 - gidx) => u64 max picks max value,
    // lowest index on ties (matches jax.lax.top_k ordering). Invalid slots = 0.
    unsigned long long a = 0ull, b = 0ull;
    if (lane < S) {
        unsigned long long k = wb[lane];
        a = ((unsigned long long)ord_bits((unsigned)(k >> 32)) << 32) | (unsigned)k;
    }
    if (lane + 32 < S) {
        unsigned long long k = wb[lane + 32];
        b = ((unsigned long long)ord_bits((unsigned)(k >> 32)) << 32) | (unsigned)k;
    }
    {
        unsigned long long mx = (a > b) ? a : b;
        b = (a > b) ? b : a;
        a = mx;
    }

    // 8 REDUX rounds; winner of round r captured by lane r (value) and lane r+8 (index).
    unsigned int rmord = 0, capv = 0, capi = 0;
#pragma unroll
    for (int r = 0; r < TOPK; r++) {
        unsigned int hi = (unsigned)(a >> 32);
        unsigned int m  = __reduce_max_sync(0xffffffffu, hi);
        bool win        = (hi == m);
        unsigned int wl = __reduce_max_sync(0xffffffffu, win ? (unsigned)a : 0u);
        if (r == 0) rmord = m;                    // row max (warp-uniform)
        capv = (lane == r)     ? m  : capv;
        capi = (lane == r + 8) ? wl : capi;
        bool adv = win && ((unsigned)a == wl);
        a = adv ? b : a;
        b = adv ? 0ull : b;
    }

    // ---- Softmax denominator over all 256 ----
    const float rowmax = ord2f(rmord);
    const float rm2 = rowmax * LOG2E;
    float sm = 0.f;
#pragma unroll
    for (int j = 0; j < 8; j++) sm += ex2(fmaf(v[j], LOG2E, -rm2));
#pragma unroll
    for (int o2 = 16; o2 > 0; o2 >>= 1) sm += __shfl_xor_sync(0xffffffffu, sm, o2);
    const float inv = 1.0f / sm;

    // ---- Thin epilogue: one exp / one i2f per output lane ----
    // Layout: [weights (TOKENS*8) | indices-as-float (TOKENS*8)]
    if (lane < TOPK) {
        float w = ex2(fmaf(ord2f(capv), LOG2E, -rm2)) * inv;
        out[(size_t)warp * TOPK + lane] = w;
    } else if (lane < 2 * TOPK) {
        out[(size_t)NUM_TOKENS * TOPK + (size_t)warp * TOPK + (lane - TOPK)]
            = (float)(int)(255u - capi);
    }
}

extern "C" void kernel_launch(void* const* d_in, const int* in_sizes, int n_in,
                              void* d_out, int out_size) {
    const float* gating = (const float*)d_in[0];
    float* out = (float*)d_out;
    const int blocks = NUM_TOKENS / 8;   // 8 warps (tokens) per 256-thread block
    moe_topk_softmax_kernel<<<blocks, 256>>>(gating, out);
}